// round 6
// baseline (speedup 1.0000x reference)
#include <cuda_runtime.h>
#include <cuda_fp16.h>
#include <cstdint>

#define DEVFN __device__ __forceinline__

// Sizes: B=256, S=256, 2H=1024, U=512, 4H=2048
__device__ __align__(16) __half g_W1h[512 * 2048];
__device__ __align__(16) __half g_W2h[512 * 1024];
__device__ __align__(16) __half g_qh [256 * 2048];
__device__ float g_qp[256 * 512];

// ---------------- helpers ----------------
DEVFN uint32_t smem_u32(const void* p) {
    uint32_t a;
    asm("{.reg .u64 t; cvta.to.shared.u64 t,%1; cvt.u32.u64 %0,t;}" : "=r"(a) : "l"(p));
    return a;
}
DEVFN uint32_t f2h2(float lo, float hi) { // low half = lo
    uint32_t u;
    asm("cvt.rn.f16x2.f32 %0,%1,%2;" : "=r"(u) : "f"(hi), "f"(lo));
    return u;
}
DEVFN float tanh_fast(float x) {
    float y;
    asm("tanh.approx.f32 %0,%1;" : "=f"(y) : "f"(x));
    return y;
}
DEVFN void ldsm4(uint32_t* r, uint32_t addr) {
    asm volatile("ldmatrix.sync.aligned.m8n8.x4.shared.b16 {%0,%1,%2,%3},[%4];"
                 : "=r"(r[0]), "=r"(r[1]), "=r"(r[2]), "=r"(r[3]) : "r"(addr));
}
DEVFN void ldsm2(uint32_t* r, uint32_t addr) {
    asm volatile("ldmatrix.sync.aligned.m8n8.x2.shared.b16 {%0,%1},[%2];"
                 : "=r"(r[0]), "=r"(r[1]) : "r"(addr));
}
DEVFN void mma16816(float* c, const uint32_t* a, const uint32_t* b) {
    asm volatile(
        "mma.sync.aligned.m16n8k16.row.col.f32.f16.f16.f32 "
        "{%0,%1,%2,%3}, {%4,%5,%6,%7}, {%8,%9}, {%0,%1,%2,%3};"
        : "+f"(c[0]), "+f"(c[1]), "+f"(c[2]), "+f"(c[3])
        : "r"(a[0]), "r"(a[1]), "r"(a[2]), "r"(a[3]), "r"(b[0]), "r"(b[1]));
}
DEVFN void sts4(uint32_t addr, uint32_t x, uint32_t y, uint32_t z, uint32_t w) {
    asm volatile("st.shared.v4.b32 [%0],{%1,%2,%3,%4};"
                 :: "r"(addr), "r"(x), "r"(y), "r"(z), "r"(w) : "memory");
}
#define SW128(bo) ((bo) ^ (((bo) >> 3) & 0x70))

// ============================================================================
// Warp-MMA GEMM tile: 64 rows (m) x 32*NF cols (n), K = nkc*64, fp16 in/f32 acc
// 256 threads = 8 warps in 2(m) x 4(n): warp tile 32 x (NF*8).
// A: 64 x K  (AF32: fp32 source, converted on the fly). B: (32*NF) x K fp16.
// SMEM: sA 8KB (64 x 128B swizzled), sB NF*4KB (32*NF x 128B swizzled).
// NOTE: k-step offsets into swizzled addresses are XORed (ks*32 touches bits
// 5-6, which the SW128 swizzle also affects); row offsets (+2048, +nf*1024)
// are plain adds (bits >=10, swizzle-invariant).
// ============================================================================
template <int NF, bool AF32>
DEVFN void gemm_tile(const void* __restrict__ Asrc, int lda,
                     const __half* __restrict__ Bsrc, int ldb,
                     int nkc, uint32_t sA, uint32_t sB,
                     float (&acc)[2][NF][4], int tid) {
    const int lane = tid & 31, wid = tid >> 5;
    const int wm = wid >> 2, wn = wid & 3;

#pragma unroll
    for (int mf = 0; mf < 2; mf++)
#pragma unroll
        for (int nf = 0; nf < NF; nf++)
#pragma unroll
            for (int r = 0; r < 4; r++) acc[mf][nf][r] = 0.f;

    uint32_t abo = (uint32_t)(wm * 32 + (lane & 15)) * 128 + ((lane >> 4) << 4);
    uint32_t aswz = sA + SW128(abo);
    uint32_t bbo = (uint32_t)(wn * NF * 8 + (lane & 7)) * 128 + (((lane >> 3) & 1) << 4);
    uint32_t bswz = sB + SW128(bbo);

#pragma unroll 1
    for (int kc = 0; kc < nkc; kc++) {
        __syncthreads();  // previous chunk's ldmatrix done before overwrite
        // ---- stage A chunk: 64 rows x 64 cols -> fp16 swizzled ----
#pragma unroll
        for (int i = 0; i < 2; i++) {
            int w = tid + i * 256;          // 512 16B-units
            int r = w >> 3, c = w & 7;
            uint32_t dst = sA + SW128((uint32_t)(r * 128 + c * 16));
            if (AF32) {
                const float* ap = (const float*)Asrc + (size_t)r * lda + kc * 64 + c * 8;
                float4 v0 = *(const float4*)ap;
                float4 v1 = *(const float4*)(ap + 4);
                sts4(dst, f2h2(v0.x, v0.y), f2h2(v0.z, v0.w),
                          f2h2(v1.x, v1.y), f2h2(v1.z, v1.w));
            } else {
                const __half* ap = (const __half*)Asrc + (size_t)r * lda + kc * 64 + c * 8;
                uint4 v = *(const uint4*)ap;
                sts4(dst, v.x, v.y, v.z, v.w);
            }
        }
        // ---- stage B chunk: 32*NF rows x 64 cols fp16 swizzled ----
#pragma unroll
        for (int i = 0; i < NF; i++) {
            int w = tid + i * 256;
            int r = w >> 3, c = w & 7;
            const __half* bp = Bsrc + (size_t)r * ldb + kc * 64 + c * 8;
            uint4 v = *(const uint4*)bp;
            sts4(sB + SW128((uint32_t)(r * 128 + c * 16)), v.x, v.y, v.z, v.w);
        }
        __syncthreads();
        // ---- compute: 4 k16 steps ----
#pragma unroll
        for (int ks = 0; ks < 4; ks++) {
            uint32_t a[2][4];
            ldsm4(a[0], aswz ^ (uint32_t)(ks * 32));
            ldsm4(a[1], (aswz + 2048) ^ (uint32_t)(ks * 32));
#pragma unroll
            for (int nf = 0; nf < NF; nf++) {
                uint32_t b[2];
                ldsm2(b, (bswz + nf * 1024) ^ (uint32_t)(ks * 32));
                mma16816(acc[0][nf], a[0], b);
                mma16816(acc[1][nf], a[1], b);
            }
        }
    }
}

// ---------------- kernel 0: fp32 -> fp16 conversions ----------------
__global__ void cvt_kernel(const float* __restrict__ W1, const float* __restrict__ W2,
                           const float* __restrict__ dec) {
    int stride = gridDim.x * blockDim.x;
    int i0 = blockIdx.x * blockDim.x + threadIdx.x;
    for (int k = i0; k < 512 * 2048; k += stride) g_W1h[k] = __float2half(W1[k]);
    for (int k = i0; k < 512 * 1024; k += stride) g_W2h[k] = __float2half(W2[k]);
    for (int k = i0; k < 256 * 2048; k += stride) g_qh[k]  = __float2half(dec[k]);
}

// ---------------- kernel 1: qp = q @ W1^T + W1_b ----------------
// grid 8: mt = bx&3 (64 q-rows), nh = bx>>2 (256 u-cols). NF=8.
__global__ void __launch_bounds__(256, 1)
qp_kernel(const float* __restrict__ W1_b) {
    extern __shared__ char dsm[];
    char* base = (char*)((((uintptr_t)dsm) + 1023) & ~(uintptr_t)1023);
    uint32_t sb = smem_u32(base);
    const uint32_t sA = sb, sB = sb + 8192;  // 8KB + 32KB

    int tid = threadIdx.x, lane = tid & 31, wid = tid >> 5;
    int wm = wid >> 2, wn = wid & 3;
    int mt = blockIdx.x & 3, nh = blockIdx.x >> 2;

    float acc[2][8][4];
    gemm_tile<8, false>(g_qh + (size_t)mt * 64 * 2048, 2048,
                        g_W1h + (size_t)nh * 256 * 2048, 2048,
                        32, sA, sB, acc, tid);

#pragma unroll
    for (int mf = 0; mf < 2; mf++) {
        int r0 = mt * 64 + wm * 32 + mf * 16 + (lane >> 2);
#pragma unroll
        for (int nf = 0; nf < 8; nf++) {
            int u = nh * 256 + wn * 64 + nf * 8 + (lane & 3) * 2;
            float2 bias = *(const float2*)&W1_b[u];
            *(float2*)&g_qp[r0 * 512 + u] =
                make_float2(acc[mf][nf][0] + bias.x, acc[mf][nf][1] + bias.y);
            *(float2*)&g_qp[(r0 + 8) * 512 + u] =
                make_float2(acc[mf][nf][2] + bias.x, acc[mf][nf][3] + bias.y);
        }
    }
}

// ---------------- kernel 2: fused k_proj GEMM + tanh/V + softmax + context ---
// One CTA per batch. enc row r = b*256+s (raw reshape of [S,B,2H]).
// out = [context 256x1024 | weights 256x256]
__global__ void __launch_bounds__(256, 1)
attn_main(const float* __restrict__ enc, const float* __restrict__ W2_b,
          const float* __restrict__ V_w, float* __restrict__ out) {
    extern __shared__ char dsm[];
    char* base = (char*)((((uintptr_t)dsm) + 1023) & ~(uintptr_t)1023);
    uint32_t sb = smem_u32(base);
    const uint32_t sA = sb, sB = sb + 8192;          // 8KB + 64KB
    float2* comboV = (float2*)(base + 73728);        // 512 x {combo, V}
    float*  score4 = (float*)(base + 77824);         // 256 rows x 4 n-warps
    float*  wts    = (float*)(base + 81920);         // 256
    float*  red    = (float*)(base + 82944);         // 16

    int tid = threadIdx.x, lane = tid & 31, wid = tid >> 5;
    int wm = wid >> 2, wn = wid & 3;
    int b = blockIdx.x;

    for (int u = tid; u < 512; u += 256)
        comboV[u] = make_float2(g_qp[b * 512 + u] + W2_b[u], V_w[u]);

    const float* encb = enc + (size_t)b * 256 * 1024;

#pragma unroll 1
    for (int mt = 0; mt < 4; mt++) {
        float acc[2][16][4];
        gemm_tile<16, true>(encb + (size_t)mt * 64 * 1024, 1024,
                            g_W2h, 1024, 16, sA, sB, acc, tid);
        // epilogue: score_s += sum_u V[u]*tanh(combo[u] + kp[s,u])
#pragma unroll
        for (int mf = 0; mf < 2; mf++) {
            float p0 = 0.f, p1 = 0.f;
#pragma unroll
            for (int nf = 0; nf < 16; nf++) {
                int u = wn * 128 + nf * 8 + (lane & 3) * 2;
                float2 cv0 = comboV[u], cv1 = comboV[u + 1];
                p0 += cv0.y * tanh_fast(cv0.x + acc[mf][nf][0])
                    + cv1.y * tanh_fast(cv1.x + acc[mf][nf][1]);
                p1 += cv0.y * tanh_fast(cv0.x + acc[mf][nf][2])
                    + cv1.y * tanh_fast(cv1.x + acc[mf][nf][3]);
            }
            p0 += __shfl_xor_sync(~0u, p0, 1); p0 += __shfl_xor_sync(~0u, p0, 2);
            p1 += __shfl_xor_sync(~0u, p1, 1); p1 += __shfl_xor_sync(~0u, p1, 2);
            if ((lane & 3) == 0) {
                int r = mt * 64 + wm * 32 + mf * 16 + (lane >> 2);
                score4[r * 4 + wn] = p0;        // deterministic: (r, wn) unique
                score4[(r + 8) * 4 + wn] = p1;
            }
        }
    }
    __syncthreads();

    // softmax over 256 scores (V_b constant across s -> cancels)
    float s0 = score4[tid * 4] + score4[tid * 4 + 1] + score4[tid * 4 + 2] + score4[tid * 4 + 3];
    float m = s0;
#pragma unroll
    for (int o = 16; o; o >>= 1) m = fmaxf(m, __shfl_xor_sync(~0u, m, o));
    if (lane == 0) red[wid] = m;
    __syncthreads();
    m = red[0];
#pragma unroll
    for (int i = 1; i < 8; i++) m = fmaxf(m, red[i]);
    float e = __expf(s0 - m);
    float sum = e;
#pragma unroll
    for (int o = 16; o; o >>= 1) sum += __shfl_xor_sync(~0u, sum, o);
    if (lane == 0) red[8 + wid] = sum;
    __syncthreads();
    sum = red[8];
#pragma unroll
    for (int i = 1; i < 8; i++) sum += red[8 + i];
    float w = e * (1.f / sum);
    wts[tid] = w;
    out[262144 + b * 256 + tid] = w;
    __syncthreads();

    // context[e] = sum_s w[s] * enc[b,s,e]; thread owns float4 column tid
    const float4* e4 = (const float4*)encb;
    float4 a = make_float4(0.f, 0.f, 0.f, 0.f);
#pragma unroll 4
    for (int s = 0; s < 256; s++) {
        float ws = wts[s];
        float4 v = e4[s * 256 + tid];
        a.x += ws * v.x; a.y += ws * v.y; a.z += ws * v.z; a.w += ws * v.w;
    }
    ((float4*)(out + (size_t)b * 1024))[tid] = a;
}

// ---------------- launch ----------------
extern "C" void kernel_launch(void* const* d_in, const int* in_sizes, int n_in,
                              void* d_out, int out_size) {
    (void)in_sizes; (void)n_in; (void)out_size;
    const float* dec = (const float*)d_in[0];
    const float* enc = (const float*)d_in[1];
    const float* W1w = (const float*)d_in[2];
    const float* W1b = (const float*)d_in[3];
    const float* W2w = (const float*)d_in[4];
    const float* W2b = (const float*)d_in[5];
    const float* Vw  = (const float*)d_in[6];
    // d_in[7] = V_b: constant over s, cancels in softmax
    float* out = (float*)d_out;

    cudaFuncSetAttribute(qp_kernel, cudaFuncAttributeMaxDynamicSharedMemorySize, 44032);
    cudaFuncSetAttribute(attn_main, cudaFuncAttributeMaxDynamicSharedMemorySize, 86016);

    cvt_kernel<<<1024, 256>>>(W1w, W2w, dec);
    qp_kernel<<<8, 256, 44032>>>(W1b);
    attn_main<<<256, 256, 86016>>>(enc, W2b, Vw, out);
}

// round 8
// speedup vs baseline: 1.4737x; 1.4737x over previous
#include <cuda_runtime.h>
#include <cuda_fp16.h>
#include <cstdint>

#define DEVFN __device__ __forceinline__

// Sizes: B=256, S=256, 2H=1024, U=512, 4H=2048
__device__ __align__(16) __half g_W1h[512 * 2048];
__device__ __align__(16) __half g_W2h[512 * 1024];
__device__ __align__(16) __half g_qh [256 * 2048];
__device__ float g_qp[256 * 512];

// ---------------- helpers ----------------
DEVFN uint32_t smem_u32(const void* p) {
    uint32_t a;
    asm("{.reg .u64 t; cvta.to.shared.u64 t,%1; cvt.u32.u64 %0,t;}" : "=r"(a) : "l"(p));
    return a;
}
DEVFN uint32_t f2h2(float lo, float hi) { // low half = lo
    uint32_t u;
    asm("cvt.rn.f16x2.f32 %0,%1,%2;" : "=r"(u) : "f"(hi), "f"(lo));
    return u;
}
DEVFN float tanh_fast(float x) {
    float y;
    asm("tanh.approx.f32 %0,%1;" : "=f"(y) : "f"(x));
    return y;
}
DEVFN void ldsm4(uint32_t* r, uint32_t addr) {
    asm volatile("ldmatrix.sync.aligned.m8n8.x4.shared.b16 {%0,%1,%2,%3},[%4];"
                 : "=r"(r[0]), "=r"(r[1]), "=r"(r[2]), "=r"(r[3]) : "r"(addr));
}
DEVFN void mma16816(float* c, const uint32_t* a, const uint32_t* b) {
    asm volatile(
        "mma.sync.aligned.m16n8k16.row.col.f32.f16.f16.f32 "
        "{%0,%1,%2,%3}, {%4,%5,%6,%7}, {%8,%9}, {%0,%1,%2,%3};"
        : "+f"(c[0]), "+f"(c[1]), "+f"(c[2]), "+f"(c[3])
        : "r"(a[0]), "r"(a[1]), "r"(a[2]), "r"(a[3]), "r"(b[0]), "r"(b[1]));
}
DEVFN void sts4(uint32_t addr, uint32_t x, uint32_t y, uint32_t z, uint32_t w) {
    asm volatile("st.shared.v4.b32 [%0],{%1,%2,%3,%4};"
                 :: "r"(addr), "r"(x), "r"(y), "r"(z), "r"(w) : "memory");
}
DEVFN void cp16(uint32_t dst, const void* src) {
    asm volatile("cp.async.cg.shared.global [%0],[%1],16;" :: "r"(dst), "l"(src) : "memory");
}
#define CP_COMMIT() asm volatile("cp.async.commit_group;" ::: "memory")
#define CP_WAIT0()  asm volatile("cp.async.wait_group 0;" ::: "memory")
#define SW128(bo) ((bo) ^ (((bo) >> 3) & 0x70))

// ============================================================================
// Pipelined warp-MMA GEMM tile: 64 m-rows x 32*NF n-cols, K = nkc*64.
// 256 threads = 8 warps (2m x 4n); warp tile 32 x NF*8; fp16 in / fp32 acc.
// SMEM: sA = 2 x 8KB double buffer; sB = 2 x NF*4KB double buffer (SW128).
// B staged via cp.async. A: fp32 source -> register prefetch + cvt + STS;
// fp16 source -> cp.async alongside B.
// Swizzle rule: k-step offsets (ks*32, bits 5-6) are XORed into swizzled
// addresses; row offsets (>=bit 10) are plain adds.
// ============================================================================
template <int NF, bool AF32>
DEVFN void gemm_tile(const void* __restrict__ Asrc, int lda,
                     const __half* __restrict__ Bsrc, int ldb,
                     int nkc, uint32_t sA, uint32_t sB,
                     float (&acc)[2][NF][4], int tid) {
    const int lane = tid & 31, wid = tid >> 5;
    const int wm = wid >> 2, wn = wid & 3;
    constexpr uint32_t BBUF = NF * 4096;

#pragma unroll
    for (int mf = 0; mf < 2; mf++)
#pragma unroll
        for (int nf = 0; nf < NF; nf++)
#pragma unroll
            for (int r = 0; r < 4; r++) acc[mf][nf][r] = 0.f;

    // fragment base byte-offsets (pre-swizzle)
    const uint32_t abo = (uint32_t)(wm * 32 + (lane & 15)) * 128 + ((lane >> 4) << 4);
    const uint32_t bbo = (uint32_t)(wn * NF * 8 + (lane & 7) + ((lane >> 4) & 1) * 8) * 128
                       + (((lane >> 3) & 1) << 4);
    // staging indices: 16B unit w -> row w>>3, col w&7
    const int r0s = tid >> 3, c0s = tid & 7;          // i=0
    const int r1s = (tid + 256) >> 3, c1s = tid & 7;  // i=1

    float4 paf[4];   // A prefetch (fp32 source)

    auto ldA32 = [&](int kc) {
        const float* a0 = (const float*)Asrc + (size_t)r0s * lda + kc * 64 + c0s * 8;
        const float* a1 = (const float*)Asrc + (size_t)r1s * lda + kc * 64 + c1s * 8;
        paf[0] = *(const float4*)a0; paf[1] = *(const float4*)(a0 + 4);
        paf[2] = *(const float4*)a1; paf[3] = *(const float4*)(a1 + 4);
    };
    auto stA32 = [&](uint32_t buf) {
        sts4(buf + SW128((uint32_t)(r0s * 128 + c0s * 16)),
             f2h2(paf[0].x, paf[0].y), f2h2(paf[0].z, paf[0].w),
             f2h2(paf[1].x, paf[1].y), f2h2(paf[1].z, paf[1].w));
        sts4(buf + SW128((uint32_t)(r1s * 128 + c1s * 16)),
             f2h2(paf[2].x, paf[2].y), f2h2(paf[2].z, paf[2].w),
             f2h2(paf[3].x, paf[3].y), f2h2(paf[3].z, paf[3].w));
    };
    auto issue_async = [&](int kc, uint32_t bufA, uint32_t bufB) {
        if (!AF32) {  // A fp16: cp.async 2x16B
            cp16(bufA + SW128((uint32_t)(r0s * 128 + c0s * 16)),
                 (const __half*)Asrc + (size_t)r0s * lda + kc * 64 + c0s * 8);
            cp16(bufA + SW128((uint32_t)(r1s * 128 + c1s * 16)),
                 (const __half*)Asrc + (size_t)r1s * lda + kc * 64 + c1s * 8);
        }
#pragma unroll
        for (int i = 0; i < NF; i++) {
            int w = tid + i * 256;
            int r = w >> 3, c = w & 7;
            cp16(bufB + SW128((uint32_t)(r * 128 + c * 16)),
                 Bsrc + (size_t)r * ldb + kc * 64 + c * 8);
        }
        CP_COMMIT();
    };

    // prologue: stage chunk 0
    issue_async(0, sA, sB);
    if (AF32) ldA32(0);

#pragma unroll 1
    for (int kc = 0; kc < nkc; kc++) {
        const uint32_t curA = sA + (uint32_t)(kc & 1) * 8192;
        const uint32_t curB = sB + (uint32_t)(kc & 1) * BBUF;
        if (AF32) stA32(curA);           // safe: readers of curA finished 2 iters ago
        CP_WAIT0();                      // chunk kc's async group arrived
        __syncthreads();                 // everyone sees A(kc), B(kc); old readers done
        if (kc + 1 < nkc) {
            issue_async(kc + 1, sA + (uint32_t)((kc + 1) & 1) * 8192,
                                sB + (uint32_t)((kc + 1) & 1) * BBUF);
            if (AF32) ldA32(kc + 1);     // overlaps compute below
        }
        const uint32_t aswz = curA + SW128(abo);
        const uint32_t bswz = curB + SW128(bbo);
#pragma unroll
        for (int ks = 0; ks < 4; ks++) {
            uint32_t a0[4], a1[4];
            ldsm4(a0, aswz ^ (uint32_t)(ks * 32));
            ldsm4(a1, (aswz + 2048) ^ (uint32_t)(ks * 32));
#pragma unroll
            for (int p = 0; p < NF / 2; p++) {
                uint32_t b4[4];          // {nf=2p klo, khi, nf=2p+1 klo, khi}
                ldsm4(b4, (bswz + p * 2048) ^ (uint32_t)(ks * 32));
                mma16816(acc[0][2 * p],     a0, b4);
                mma16816(acc[1][2 * p],     a1, b4);
                mma16816(acc[0][2 * p + 1], a0, b4 + 2);
                mma16816(acc[1][2 * p + 1], a1, b4 + 2);
            }
        }
    }
}

// ---------------- kernel 0: fp32 -> fp16 conversions ----------------
__global__ void cvt_kernel(const float* __restrict__ W1, const float* __restrict__ W2,
                           const float* __restrict__ dec) {
    int stride = gridDim.x * blockDim.x;
    int i0 = blockIdx.x * blockDim.x + threadIdx.x;
    for (int k = i0; k < 512 * 2048; k += stride) g_W1h[k] = __float2half(W1[k]);
    for (int k = i0; k < 512 * 1024; k += stride) g_W2h[k] = __float2half(W2[k]);
    for (int k = i0; k < 256 * 2048; k += stride) g_qh[k]  = __float2half(dec[k]);
}

// ---------------- kernel 1: qp = q @ W1^T + W1_b ----------------
// grid 8: mt = bx&3 (64 q-rows), nh = bx>>2 (256 u-cols). NF=8, K=2048.
__global__ void __launch_bounds__(256, 1)
qp_kernel(const float* __restrict__ W1_b) {
    extern __shared__ char dsm[];
    char* base = (char*)((((uintptr_t)dsm) + 1023) & ~(uintptr_t)1023);
    uint32_t sb = smem_u32(base);
    const uint32_t sA = sb, sB = sb + 16384;  // A 2x8KB, B 2x32KB

    int tid = threadIdx.x, lane = tid & 31, wid = tid >> 5;
    int wm = wid >> 2, wn = wid & 3;
    int mt = blockIdx.x & 3, nh = blockIdx.x >> 2;

    float acc[2][8][4];
    gemm_tile<8, false>(g_qh + (size_t)mt * 64 * 2048, 2048,
                        g_W1h + (size_t)nh * 256 * 2048, 2048,
                        32, sA, sB, acc, tid);

#pragma unroll
    for (int mf = 0; mf < 2; mf++) {
        int r0 = mt * 64 + wm * 32 + mf * 16 + (lane >> 2);
#pragma unroll
        for (int nf = 0; nf < 8; nf++) {
            int u = nh * 256 + wn * 64 + nf * 8 + (lane & 3) * 2;
            float2 bias = *(const float2*)&W1_b[u];
            *(float2*)&g_qp[r0 * 512 + u] =
                make_float2(acc[mf][nf][0] + bias.x, acc[mf][nf][1] + bias.y);
            *(float2*)&g_qp[(r0 + 8) * 512 + u] =
                make_float2(acc[mf][nf][2] + bias.x, acc[mf][nf][3] + bias.y);
        }
    }
}

// ---------------- kernel 2: fused k_proj GEMM + tanh/V + softmax + context ---
// One CTA per batch. enc row r = b*256+s (raw reshape of [S,B,2H]).
// out = [context 256x1024 | weights 256x256]
__global__ void __launch_bounds__(256, 1)
attn_main(const float* __restrict__ enc, const float* __restrict__ W2_b,
          const float* __restrict__ V_w, float* __restrict__ out) {
    extern __shared__ char dsm[];
    char* base = (char*)((((uintptr_t)dsm) + 1023) & ~(uintptr_t)1023);
    uint32_t sb = smem_u32(base);
    const uint32_t sA = sb, sB = sb + 16384;         // A 2x8KB, B 2x64KB -> 147456
    float2* comboV = (float2*)(base + 147456);       // 512 x {combo, V}
    float*  score4 = (float*)(base + 151552);        // 256 rows x 4 n-warps
    float*  wts    = (float*)(base + 155648);        // 256
    float*  red    = (float*)(base + 156672);        // 16

    int tid = threadIdx.x, lane = tid & 31, wid = tid >> 5;
    int wm = wid >> 2, wn = wid & 3;
    int b = blockIdx.x;

    for (int u = tid; u < 512; u += 256)
        comboV[u] = make_float2(g_qp[b * 512 + u] + W2_b[u], V_w[u]);

    const float* encb = enc + (size_t)b * 256 * 1024;

#pragma unroll 1
    for (int mt = 0; mt < 4; mt++) {
        float acc[2][16][4];
        gemm_tile<16, true>(encb + (size_t)mt * 64 * 1024, 1024,
                            g_W2h, 1024, 16, sA, sB, acc, tid);
        // epilogue: score_s += sum_u V[u]*tanh(combo[u] + kp[s,u])
#pragma unroll
        for (int mf = 0; mf < 2; mf++) {
            float p0 = 0.f, p1 = 0.f;
#pragma unroll
            for (int nf = 0; nf < 16; nf++) {
                int u = wn * 128 + nf * 8 + (lane & 3) * 2;
                float2 cv0 = comboV[u], cv1 = comboV[u + 1];
                p0 += cv0.y * tanh_fast(cv0.x + acc[mf][nf][0])
                    + cv1.y * tanh_fast(cv1.x + acc[mf][nf][1]);
                p1 += cv0.y * tanh_fast(cv0.x + acc[mf][nf][2])
                    + cv1.y * tanh_fast(cv1.x + acc[mf][nf][3]);
            }
            p0 += __shfl_xor_sync(~0u, p0, 1); p0 += __shfl_xor_sync(~0u, p0, 2);
            p1 += __shfl_xor_sync(~0u, p1, 1); p1 += __shfl_xor_sync(~0u, p1, 2);
            if ((lane & 3) == 0) {
                int r = mt * 64 + wm * 32 + mf * 16 + (lane >> 2);
                score4[r * 4 + wn] = p0;        // deterministic: (r, wn) unique
                score4[(r + 8) * 4 + wn] = p1;
            }
        }
    }
    __syncthreads();

    // softmax over 256 scores (V_b constant across s -> cancels)
    float s0 = score4[tid * 4] + score4[tid * 4 + 1] + score4[tid * 4 + 2] + score4[tid * 4 + 3];
    float m = s0;
#pragma unroll
    for (int o = 16; o; o >>= 1) m = fmaxf(m, __shfl_xor_sync(~0u, m, o));
    if (lane == 0) red[wid] = m;
    __syncthreads();
    m = red[0];
#pragma unroll
    for (int i = 1; i < 8; i++) m = fmaxf(m, red[i]);
    float e = __expf(s0 - m);
    float sum = e;
#pragma unroll
    for (int o = 16; o; o >>= 1) sum += __shfl_xor_sync(~0u, sum, o);
    if (lane == 0) red[8 + wid] = sum;
    __syncthreads();
    sum = red[8];
#pragma unroll
    for (int i = 1; i < 8; i++) sum += red[8 + i];
    float w = e * (1.f / sum);
    wts[tid] = w;
    out[262144 + b * 256 + tid] = w;
    __syncthreads();

    // context[e] = sum_s w[s] * enc[b,s,e]; thread owns float4 column tid
    const float4* e4 = (const float4*)encb;
    float4 a = make_float4(0.f, 0.f, 0.f, 0.f);
#pragma unroll 4
    for (int s = 0; s < 256; s++) {
        float ws = wts[s];
        float4 v = e4[s * 256 + tid];
        a.x += ws * v.x; a.y += ws * v.y; a.z += ws * v.z; a.w += ws * v.w;
    }
    ((float4*)(out + (size_t)b * 1024))[tid] = a;
}

// ---------------- launch ----------------
extern "C" void kernel_launch(void* const* d_in, const int* in_sizes, int n_in,
                              void* d_out, int out_size) {
    (void)in_sizes; (void)n_in; (void)out_size;
    const float* dec = (const float*)d_in[0];
    const float* enc = (const float*)d_in[1];
    const float* W1w = (const float*)d_in[2];
    const float* W1b = (const float*)d_in[3];
    const float* W2w = (const float*)d_in[4];
    const float* W2b = (const float*)d_in[5];
    const float* Vw  = (const float*)d_in[6];
    // d_in[7] = V_b: constant over s, cancels in softmax
    float* out = (float*)d_out;

    cudaFuncSetAttribute(qp_kernel, cudaFuncAttributeMaxDynamicSharedMemorySize, 83968);
    cudaFuncSetAttribute(attn_main, cudaFuncAttributeMaxDynamicSharedMemorySize, 159744);

    cvt_kernel<<<1024, 256>>>(W1w, W2w, dec);
    qp_kernel<<<8, 256, 83968>>>(W1b);
    attn_main<<<256, 256, 159744>>>(enc, W2b, Vw, out);
}